// round 9
// baseline (speedup 1.0000x reference)
#include <cuda_runtime.h>
#include <math.h>

#define T_STEPS 512
#define BATCH   512
#define IN_DIM  4
#define AUX_DIM 28
#define OUT_DIM 32
#define G_DIM   64
#define NROWS   1184      // 128 (W_i) + 1024 (W_r) + 32 (W_o)
#define NCTA    128
#define NTHREADS 640
#define NGEMM   (NROWS / 2)   // 592 GEMM threads, 2 rows each
#define R_SM    704           // Wcat rows cached in smem (tid < 352)

typedef unsigned long long ull;

// ---------------- device globals ----------------
__device__ float g_WcatT[G_DIM * NROWS];   // [g][row]
__device__ float g_bcat[NROWS];
__device__ float g_E[OUT_DIM * G_DIM];     // exp(W_s)        [o][g]
__device__ float g_sWr[G_DIM * OUT_DIM];   // sigmoid(W_rm.T) [g][o]
__device__ float g_d0[G_DIM];              // b0 @ exp(W_s)   [g]
__device__ ull   g_msg[2][NCTA * 4];       // (tag<<32)|float partial, 4 per CTA

__device__ __forceinline__ float sigm(float x) {
    return __fdividef(1.0f, 1.0f + __expf(-x));
}
__device__ __forceinline__ float tanh_fast(float x) {
    x = fminf(fmaxf(x, -12.0f), 12.0f);
    float e = __expf(2.0f * x);
    return __fdividef(e - 1.0f, e + 1.0f);
}
__device__ __forceinline__ float wsum32(float v) {
#pragma unroll
    for (int s = 16; s > 0; s >>= 1) v += __shfl_xor_sync(0xffffffffu, v, s);
    return v;
}
__device__ __forceinline__ void ffma2(ull& d, ull a, ull b) {
    asm("fma.rn.f32x2 %0, %1, %2, %0;" : "+l"(d) : "l"(a), "l"(b));
}
__device__ __forceinline__ ull dup2(float x) {
    ull r; asm("mov.b64 %0, {%1, %1};" : "=l"(r) : "f"(x)); return r;
}
__device__ __forceinline__ float2 unp(ull v) {
    float2 r;
    r.x = __uint_as_float((unsigned)v);
    r.y = __uint_as_float((unsigned)(v >> 32));
    return r;
}
__device__ __forceinline__ void ld_vol_v2u64(const ull* p, ull& a, ull& b) {
    asm volatile("ld.volatile.global.v2.u64 {%0, %1}, [%2];"
                 : "=l"(a), "=l"(b) : "l"(p) : "memory");
}

// per-g inner op: 4 batch accumulators per half, 2 rows packed in each ull
#define MM4(ACC, F01, F23, W) \
    ffma2(ACC[0], F01.x, W); ffma2(ACC[1], F01.y, W); \
    ffma2(ACC[2], F23.x, W); ffma2(ACC[3], F23.y, W);

// ---------------- prep: pack weights, derived constants, reset sync ----------------
__global__ void prep_kernel(const float* __restrict__ W_i, const float* __restrict__ b_i,
                            const float* __restrict__ W_r, const float* __restrict__ b_r,
                            const float* __restrict__ W_o, const float* __restrict__ b_o,
                            const float* __restrict__ W_s, const float* __restrict__ W_rm,
                            const float* __restrict__ b0)
{
    int idx = blockIdx.x * blockDim.x + threadIdx.x;
    if (idx < G_DIM * NROWS) {
        int g = idx / NROWS, r = idx % NROWS;
        float v;
        if (r < 128)        v = W_i[r * G_DIM + g];
        else if (r < 1152)  v = W_r[(r - 128) * G_DIM + g];
        else                v = W_o[(r - 1152) * G_DIM + g];
        g_WcatT[idx] = v;
    }
    int i2 = idx - G_DIM * NROWS;
    if (i2 >= 0 && i2 < NROWS)
        g_bcat[i2] = (i2 < 128) ? b_i[i2] : (i2 < 1152) ? b_r[i2 - 128] : b_o[i2 - 1152];
    int i3 = i2 - NROWS;
    if (i3 >= 0 && i3 < OUT_DIM * G_DIM) g_E[i3] = expf(W_s[i3]);
    int i4 = i3 - OUT_DIM * G_DIM;
    if (i4 >= 0 && i4 < G_DIM * OUT_DIM) {
        int g = i4 / OUT_DIM, o = i4 % OUT_DIM;
        g_sWr[i4] = 1.0f / (1.0f + expf(-W_rm[o * G_DIM + g]));
    }
    int i5 = i4 - G_DIM * OUT_DIM;
    if (i5 >= 0 && i5 < G_DIM) {
        float a = 0.0f;
        for (int o = 0; o < OUT_DIM; ++o) a += b0[o] * expf(W_s[o * G_DIM + i5]);
        g_d0[i5] = a;
    }
    int i6 = i5 - G_DIM;
    if (i6 >= 0 && i6 < 2 * NCTA * 4) ((ull*)g_msg)[i6] = 0ull;
}

// ---------------- smem layout (float offsets) ----------------
#define OFF_WS    0
#define OFF_E     (OFF_WS + G_DIM * R_SM)         // 45056
#define OFF_SWR   (OFF_E + 2048)
#define OFF_BC    (OFF_SWR + 2048)
#define OFF_F1D   (OFF_BC + 1184)                 // ull[32*4]
#define OFF_CFD   (OFF_F1D + 256)                 // ull[32*4]
#define OFF_GI    (OFF_CFD + 256)                 // [4][128]
#define OFF_RR    (OFF_GI + 512)                  // [4][1024]
#define OFF_OS    (OFF_RR + 4096)                 // [4][32]
#define OFF_C     (OFF_OS + 128)                  // [4][32]
#define OFF_XM    (OFF_C + 128)                   // [4][4]
#define OFF_CR    (OFF_XM + 16)                   // [4][32]
#define OFF_CI    (OFF_CR + 128)                  // [4][4]
#define OFF_TH    (OFF_CI + 16)                   // [4][64]
#define OFF_D0    (OFF_TH + 256)                  // [64]
#define OFF_OV1   (OFF_D0 + 64)                   // [4][32]
#define OFF_LNG   (OFF_OV1 + 128)
#define OFF_LNB   (OFF_LNG + 32)
#define OFF_QS    (OFF_LNB + 32)                  // [4][64]
#define OFF_MISC  (OFF_QS + 256)                  // [8]; [4]=S
#define SMEM_FLOATS (OFF_MISC + 8)
#define SMEM_BYTES  (SMEM_FLOATS * 4)             // ~226.6 KB

__global__ void __launch_bounds__(NTHREADS, 1)
mclstm_kernel(const float* __restrict__ xm, const float* __restrict__ xa,
              const float* __restrict__ ln_g, const float* __restrict__ ln_b,
              float* __restrict__ out)
{
    extern __shared__ float sm[];
    float* Ws     = sm + OFF_WS;
    float* E_s    = sm + OFF_E;
    float* sWr_s  = sm + OFF_SWR;
    float* bc_s   = sm + OFF_BC;
    ull*   f1d    = (ull*)(sm + OFF_F1D);
    ull*   cfd    = (ull*)(sm + OFF_CFD);
    float* gi_s   = sm + OFF_GI;
    float* rr_s   = sm + OFF_RR;
    float* o_s    = sm + OFF_OS;
    float* c_s    = sm + OFF_C;
    float* xm_s   = sm + OFF_XM;
    float* coef_r = sm + OFF_CR;
    float* coef_i = sm + OFF_CI;
    float* th_s   = sm + OFF_TH;
    float* d0_s   = sm + OFF_D0;
    float* ov1_s  = sm + OFF_OV1;
    float* lng_s  = sm + OFF_LNG;
    float* lnb_s  = sm + OFF_LNB;
    float* qs     = sm + OFF_QS;
    float* misc   = sm + OFF_MISC;

    const int tid = threadIdx.x;
    const int cta = blockIdx.x;
    const int bbase = cta * 4;
    const size_t OSTRIDE = (size_t)T_STEPS * BATCH * OUT_DIM;

    // feeders: tid 512..639 (double-duty with tail GEMM warps + poller; phases don't overlap)
    const bool feeder = (tid >= 512);
    int pb = 0, pg = 0;
    float xnext = 0.0f;
    if (feeder) {
        int idx = tid - 512;
        pb = idx >> 5; pg = idx & 31;
        xnext = (pg < IN_DIM) ? xm[(size_t)(bbase + pb) * IN_DIM + pg]
                              : xa[(size_t)(bbase + pb) * AUX_DIM + (pg - IN_DIM)];
    }

    // ---- one-time smem fills ----
    for (int i = tid; i < G_DIM * R_SM; i += NTHREADS) {
        int g = i / R_SM, r = i - g * R_SM;
        Ws[i] = g_WcatT[g * NROWS + r];
    }
    for (int i = tid; i < 2048; i += NTHREADS) { E_s[i] = g_E[i]; sWr_s[i] = g_sWr[i]; }
    for (int i = tid; i < NROWS; i += NTHREADS) bc_s[i] = g_bcat[i];
    if (tid < G_DIM) d0_s[tid] = g_d0[tid];
    if (tid < OUT_DIM) { lng_s[tid] = ln_g[tid]; lnb_s[tid] = ln_b[tid]; }
    if (tid < 128) { c_s[tid] = 0.0f; cfd[tid] = 0ull; }
    for (int i = tid; i < 256; i += NTHREADS) qs[i] = 0.0f;
    if (tid < 8) misc[tid] = 0.0f;
    if (feeder) {
        f1d[pg * 4 + pb] = dup2(xnext);
        if (pg < IN_DIM) xm_s[pb * 4 + pg] = xnext;
    }

    for (int t = 0; t < T_STEPS; ++t) {
        __syncthreads();   // sync A: carry state (qs, cfd, c_s, f1d) ready

        // ---- feeders prefetch next-step inputs (LDG issued early) ----
        if (feeder && t + 1 < T_STEPS) {
            xnext = (pg < IN_DIM)
                ? xm[((size_t)(t + 1) * BATCH + bbase + pb) * IN_DIM + pg]
                : xa[((size_t)(t + 1) * BATCH + bbase + pb) * AUX_DIM + (pg - IN_DIM)];
        }
        // ---- poller warp 19: gather 512 partials -> S (overlaps GEMM) ----
        if (t > 0 && tid >= 608) {
            const int lane = tid - 608;
            const unsigned tg = (unsigned)t;
            const ull* base = &g_msg[t & 1][lane * 16];
            float p;
            for (;;) {
                ull v[16];
#pragma unroll
                for (int k = 0; k < 8; ++k) ld_vol_v2u64(base + 2 * k, v[2 * k], v[2 * k + 1]);
                unsigned bad = 0;
#pragma unroll
                for (int k = 0; k < 16; ++k) bad |= ((unsigned)(v[k] >> 32)) ^ tg;
                if (bad == 0) {
                    float s0 = 0.f, s1 = 0.f;
#pragma unroll
                    for (int k = 0; k < 16; k += 2) {
                        s0 += __uint_as_float((unsigned)v[k]);
                        s1 += __uint_as_float((unsigned)v[k + 1]);
                    }
                    p = s0 + s1;
                    break;
                }
            }
            p = wsum32(p);
            if (lane == 0) misc[4] = p;
        }

        // ---- GEMM: x-half (f1d) and c-half (cfd, un-normalized), 2 rows/thread ----
        ull a1[4], a2[4];
        if (tid < NGEMM) {
#pragma unroll
            for (int k = 0; k < 4; ++k) { a1[k] = 0ull; a2[k] = 0ull; }
            const int r0 = tid * 2;
            if (tid < R_SM / 2) {
#pragma unroll 4
                for (int g = 0; g < 32; ++g) {
                    ulonglong2 f01 = *(const ulonglong2*)(f1d + g * 4);
                    ulonglong2 f23 = *(const ulonglong2*)(f1d + g * 4 + 2);
                    ull w1 = *(const ull*)(Ws + g * R_SM + r0);
                    MM4(a1, f01, f23, w1);
                    ulonglong2 c01 = *(const ulonglong2*)(cfd + g * 4);
                    ulonglong2 c23 = *(const ulonglong2*)(cfd + g * 4 + 2);
                    ull w2 = *(const ull*)(Ws + (32 + g) * R_SM + r0);
                    MM4(a2, c01, c23, w2);
                }
            } else {
#pragma unroll 4
                for (int g = 0; g < 32; ++g) {
                    ulonglong2 f01 = *(const ulonglong2*)(f1d + g * 4);
                    ulonglong2 f23 = *(const ulonglong2*)(f1d + g * 4 + 2);
                    ull w1 = __ldg((const ull*)(g_WcatT + g * NROWS + r0));
                    MM4(a1, f01, f23, w1);
                    ulonglong2 c01 = *(const ulonglong2*)(cfd + g * 4);
                    ulonglong2 c23 = *(const ulonglong2*)(cfd + g * 4 + 2);
                    ull w2 = __ldg((const ull*)(g_WcatT + (32 + g) * NROWS + r0));
                    MM4(a2, c01, c23, w2);
                }
            }
        }
        __syncthreads();   // sync B: misc[4] (S) visible; GEMM accs in regs
        const float invS = __fdividef(1.0f, misc[4] + 1e-5f);

        // ---- combine + activations ----
        if (tid < NGEMM) {
            const int r0 = tid * 2;
            float2 bb = *(const float2*)&bc_s[r0];
#pragma unroll
            for (int b = 0; b < 4; ++b) {
                float2 v1 = unp(a1[b]);
                float2 v2 = unp(a2[b]);
                float p0 = fmaf(invS, v2.x, v1.x) + bb.x;
                float p1 = fmaf(invS, v2.y, v1.y) + bb.y;
                if (r0 < 128) {
                    *(float2*)&gi_s[b * 128 + r0] = make_float2(sigm(p0), sigm(p1));
                } else if (r0 < 1152) {
                    *(float2*)&rr_s[b * 1024 + (r0 - 128)] =
                        make_float2(fmaxf(p0, 0.0f), fmaxf(p1, 0.0f));
                } else {
                    *(float2*)&o_s[b * 32 + (r0 - 1152)] = make_float2(sigm(p0), sigm(p1));
                }
            }
        }
        if (tid < 256)   // th = tanh(invS*q - d0)
            th_s[tid] = tanh_fast(fmaf(invS, qs[tid], -d0_s[tid & 63]));
        __syncthreads();   // sync C

        // ---- parallel: coef_r (0-255) | coef_i (256-271) | LN (384-511) ----
        if (tid < 256) {
            int pair = tid >> 1, half = tid & 1;
            int b = pair >> 5, n = pair & 31;
            const float* row = rr_s + b * 1024 + n * 32 + half * 16;
            float4 v0 = *(const float4*)(row);
            float4 v1 = *(const float4*)(row + 4);
            float4 v2 = *(const float4*)(row + 8);
            float4 v3 = *(const float4*)(row + 12);
            float s = ((v0.x + v0.y) + (v0.z + v0.w)) + ((v1.x + v1.y) + (v1.z + v1.w))
                    + ((v2.x + v2.y) + (v2.z + v2.w)) + ((v3.x + v3.y) + (v3.z + v3.w));
            s += __shfl_xor_sync(0xffffffffu, s, 1);
            if (!half) coef_r[pair] = __fdividef(c_s[b * 32 + n], fmaxf(s, 1e-12f));
        } else if (tid < 272) {
            int idx = tid - 256, b2 = idx >> 2, ii = idx & 3;
            const float* gb = gi_s + b2 * 128 + ii * 32;
            float s0 = 0.f, s1 = 0.f, s2 = 0.f, s3 = 0.f;
#pragma unroll
            for (int p = 0; p < 32; p += 4) {
                s0 += gb[p]; s1 += gb[p + 1]; s2 += gb[p + 2]; s3 += gb[p + 3];
            }
            float si = (s0 + s1) + (s2 + s3);
            coef_i[idx] = __fdividef(xm_s[idx], fmaxf(si, 1e-12f));
        } else if (tid >= 384 && tid < 512) {
            int idx = tid - 384, b = idx >> 5, o = idx & 31;
            const float* thb = th_s + b * 64;
            float p0 = 0.f, p1 = 0.f, p2 = 0.f, p3 = 0.f;
#pragma unroll
            for (int g = 0; g < 64; g += 4) {
                p0 = fmaf(thb[g],     sWr_s[g * 32 + o],       p0);
                p1 = fmaf(thb[g + 1], sWr_s[(g + 1) * 32 + o], p1);
                p2 = fmaf(thb[g + 2], sWr_s[(g + 2) * 32 + o], p2);
                p3 = fmaf(thb[g + 3], sWr_s[(g + 3) * 32 + o], p3);
            }
            float pre = (p0 + p1) + (p2 + p3);
            float s1v = pre, s2v = pre * pre;
#pragma unroll
            for (int sft = 16; sft > 0; sft >>= 1) {
                s1v += __shfl_xor_sync(0xffffffffu, s1v, sft);
                s2v += __shfl_xor_sync(0xffffffffu, s2v, sft);
            }
            float mu  = s1v * (1.0f / 32.0f);
            float var = fmaxf(s2v * (1.0f / 32.0f) - mu * mu, 0.0f);
            ov1_s[idx] = (pre - mu) * rsqrtf(var + 1e-5f) * lng_s[o] + lnb_s[o];
        }
        __syncthreads();   // sync D

        // ---- final: m, MR gate, outputs, carry + publish + next-step state ----
        if (tid < 128) {
            int b = tid >> 5, o = tid & 31;
            float m0, m1, m2 = 0.f, m3 = 0.f;
            m0 = coef_i[b * 4 + 0] * gi_s[b * 128 + o]
               + coef_i[b * 4 + 1] * gi_s[b * 128 + 32 + o];
            m1 = coef_i[b * 4 + 2] * gi_s[b * 128 + 64 + o]
               + coef_i[b * 4 + 3] * gi_s[b * 128 + 96 + o];
#pragma unroll
            for (int n = 0; n < 32; n += 4) {
                m0 = fmaf(coef_r[b * 32 + n],     rr_s[b * 1024 + n * 32 + o],       m0);
                m1 = fmaf(coef_r[b * 32 + n + 1], rr_s[b * 1024 + (n + 1) * 32 + o], m1);
                m2 = fmaf(coef_r[b * 32 + n + 2], rr_s[b * 1024 + (n + 2) * 32 + o], m2);
                m3 = fmaf(coef_r[b * 32 + n + 3], rr_s[b * 1024 + (n + 3) * 32 + o], m3);
            }
            float m = (m0 + m1) + (m2 + m3);

            float og  = o_s[b * 32 + o];
            float ov1 = ov1_s[b * 32 + o];
            float f = 1.0f - og;
            float ov2 = ov1 - fmaxf(ov1 - f, 0.0f);
            float MR = fmaxf(ov2 + 1.0f - f, 0.0f) + f - 1.0f;
            float opr = og + MR;
            float h = og * m;
            float cnew = (1.0f - opr) * m;
            float mrf = MR * m;

            // publish this warp's |c| row partial IMMEDIATELY (off critical path of sync A)
            float a = wsum32(fabsf(cnew));
            if (o == 0) {
                ull msg = ((ull)(unsigned)(t + 1) << 32) | (ull)__float_as_uint(a);
                *((volatile ull*)&g_msg[(t + 1) & 1][cta * 4 + b]) = msg;
            }

            size_t base = ((size_t)t * BATCH + (bbase + b)) * OUT_DIM + o;
            out[base]               = h;
            out[OSTRIDE + base]     = cnew;
            out[2 * OSTRIDE + base] = og;
            out[3 * OSTRIDE + base] = MR;
            out[4 * OSTRIDE + base] = opr;
            out[5 * OSTRIDE + base] = mrf;
            out[6 * OSTRIDE + base] = h;

            c_s[b * 32 + o] = cnew;
            cfd[o * 4 + b]  = dup2(cnew);

            // next-step q = c_new @ E via in-warp shuffle (warp == batch row)
            float qa = 0.f, qb = 0.f;
#pragma unroll
            for (int o2 = 0; o2 < 32; ++o2) {
                float cv = __shfl_sync(0xffffffffu, cnew, o2);
                qa = fmaf(cv, E_s[o2 * 64 + o],      qa);
                qb = fmaf(cv, E_s[o2 * 64 + 32 + o], qb);
            }
            qs[b * 64 + o]      = qa;
            qs[b * 64 + 32 + o] = qb;
        } else if (feeder && t + 1 < T_STEPS) {
            f1d[pg * 4 + pb] = dup2(xnext);
            if (pg < IN_DIM) xm_s[pb * 4 + pg] = xnext;
        }
    }
}

// ---------------- launch ----------------
extern "C" void kernel_launch(void* const* d_in, const int* in_sizes, int n_in,
                              void* d_out, int out_size)
{
    const float* xm   = (const float*)d_in[0];
    const float* xa   = (const float*)d_in[1];
    const float* W_i  = (const float*)d_in[2];
    const float* b_i  = (const float*)d_in[3];
    const float* W_r  = (const float*)d_in[4];
    const float* b_r  = (const float*)d_in[5];
    const float* W_o  = (const float*)d_in[6];
    const float* b_o  = (const float*)d_in[7];
    const float* W_s  = (const float*)d_in[8];
    const float* W_rm = (const float*)d_in[9];
    const float* b0   = (const float*)d_in[10];
    const float* lng  = (const float*)d_in[11];
    const float* lnb  = (const float*)d_in[12];
    float* out = (float*)d_out;

    cudaFuncSetAttribute(mclstm_kernel, cudaFuncAttributeMaxDynamicSharedMemorySize, SMEM_BYTES);

    prep_kernel<<<320, 256>>>(W_i, b_i, W_r, b_r, W_o, b_o, W_s, W_rm, b0);
    mclstm_kernel<<<NCTA, NTHREADS, SMEM_BYTES>>>(xm, xa, lng, lnb, out);
}

// round 10
// speedup vs baseline: 1.3352x; 1.3352x over previous
#include <cuda_runtime.h>
#include <math.h>

#define T_STEPS 512
#define BATCH   512
#define IN_DIM  4
#define AUX_DIM 28
#define OUT_DIM 32
#define G_DIM   64
#define NROWS   1184      // 128 (W_i) + 1024 (W_r) + 32 (W_o)
#define NCTA    128
#define NTHREADS 640
#define NGEMM   (NROWS / 2)   // 592 GEMM threads, 2 rows each
#define R_SM    704           // Wcat rows cached in smem (tid < 352)

typedef unsigned long long ull;

// ---------------- device globals ----------------
__device__ float g_WcatT[G_DIM * NROWS];   // [g][row]
__device__ float g_bcat[NROWS];
__device__ float g_E[OUT_DIM * G_DIM];     // exp(W_s)        [o][g]
__device__ float g_sWr[G_DIM * OUT_DIM];   // sigmoid(W_rm.T) [g][o]
__device__ float g_d0[G_DIM];              // b0 @ exp(W_s)   [g]
__device__ ull   g_msg[2][NCTA * 4];       // (tag<<32)|float partial, 4 per CTA

__device__ __forceinline__ float sigm(float x) {
    return __fdividef(1.0f, 1.0f + __expf(-x));
}
__device__ __forceinline__ float tanh_fast(float x) {
    x = fminf(fmaxf(x, -12.0f), 12.0f);
    float e = __expf(2.0f * x);
    return __fdividef(e - 1.0f, e + 1.0f);
}
__device__ __forceinline__ float wsum32(float v) {
#pragma unroll
    for (int s = 16; s > 0; s >>= 1) v += __shfl_xor_sync(0xffffffffu, v, s);
    return v;
}
__device__ __forceinline__ void ffma2(ull& d, ull a, ull b) {
    asm("fma.rn.f32x2 %0, %1, %2, %0;" : "+l"(d) : "l"(a), "l"(b));
}
__device__ __forceinline__ ull dup2(float x) {
    ull r; asm("mov.b64 %0, {%1, %1};" : "=l"(r) : "f"(x)); return r;
}
__device__ __forceinline__ float2 unp(ull v) {
    float2 r;
    r.x = __uint_as_float((unsigned)v);
    r.y = __uint_as_float((unsigned)(v >> 32));
    return r;
}
__device__ __forceinline__ void ld_vol_v2u64(const ull* p, ull& a, ull& b) {
    asm volatile("ld.volatile.global.v2.u64 {%0, %1}, [%2];"
                 : "=l"(a), "=l"(b) : "l"(p) : "memory");
}

// ---------------- prep: pack weights, derived constants, reset sync ----------------
__global__ void prep_kernel(const float* __restrict__ W_i, const float* __restrict__ b_i,
                            const float* __restrict__ W_r, const float* __restrict__ b_r,
                            const float* __restrict__ W_o, const float* __restrict__ b_o,
                            const float* __restrict__ W_s, const float* __restrict__ W_rm,
                            const float* __restrict__ b0)
{
    int idx = blockIdx.x * blockDim.x + threadIdx.x;
    if (idx < G_DIM * NROWS) {
        int g = idx / NROWS, r = idx % NROWS;
        float v;
        if (r < 128)        v = W_i[r * G_DIM + g];
        else if (r < 1152)  v = W_r[(r - 128) * G_DIM + g];
        else                v = W_o[(r - 1152) * G_DIM + g];
        g_WcatT[idx] = v;
    }
    int i2 = idx - G_DIM * NROWS;
    if (i2 >= 0 && i2 < NROWS)
        g_bcat[i2] = (i2 < 128) ? b_i[i2] : (i2 < 1152) ? b_r[i2 - 128] : b_o[i2 - 1152];
    int i3 = i2 - NROWS;
    if (i3 >= 0 && i3 < OUT_DIM * G_DIM) g_E[i3] = expf(W_s[i3]);
    int i4 = i3 - OUT_DIM * G_DIM;
    if (i4 >= 0 && i4 < G_DIM * OUT_DIM) {
        int g = i4 / OUT_DIM, o = i4 % OUT_DIM;
        g_sWr[i4] = 1.0f / (1.0f + expf(-W_rm[o * G_DIM + g]));
    }
    int i5 = i4 - G_DIM * OUT_DIM;
    if (i5 >= 0 && i5 < G_DIM) {
        float a = 0.0f;
        for (int o = 0; o < OUT_DIM; ++o) a += b0[o] * expf(W_s[o * G_DIM + i5]);
        g_d0[i5] = a;
    }
    int i6 = i5 - G_DIM;
    if (i6 >= 0 && i6 < 2 * NCTA * 4) ((ull*)g_msg)[i6] = 0ull;
}

// ---------------- smem layout (float offsets) ----------------
#define OFF_WS    0
#define OFF_E     (OFF_WS + G_DIM * R_SM)         // 45056
#define OFF_SWR   (OFF_E + 2048)
#define OFF_BC    (OFF_SWR + 2048)                // 1184
#define OFF_F1S   (OFF_BC + 1184)                 // float[32*4], 16B aligned
#define OFF_CFS   (OFF_F1S + 128)                 // float[32*4]
#define OFF_GI    (OFF_CFS + 128)                 // [4][128]
#define OFF_RR    (OFF_GI + 512)                  // [4][1024]
#define OFF_OS    (OFF_RR + 4096)                 // [4][32]
#define OFF_C     (OFF_OS + 128)                  // [4][32]
#define OFF_XM    (OFF_C + 128)                   // [4][4]
#define OFF_CR    (OFF_XM + 16)                   // [4][32]
#define OFF_CI    (OFF_CR + 128)                  // [4][4]
#define OFF_TH    (OFF_CI + 16)                   // [4][64]
#define OFF_D0    (OFF_TH + 256)                  // [64]
#define OFF_OV1   (OFF_D0 + 64)                   // [4][32]
#define OFF_LNG   (OFF_OV1 + 128)
#define OFF_LNB   (OFF_LNG + 32)
#define OFF_MISC  (OFF_LNB + 32)                  // [8]; [4]=S
#define SMEM_FLOATS (OFF_MISC + 8)
#define SMEM_BYTES  (SMEM_FLOATS * 4)             // ~224.5 KB

__global__ void __launch_bounds__(NTHREADS, 1)
mclstm_kernel(const float* __restrict__ xm, const float* __restrict__ xa,
              const float* __restrict__ ln_g, const float* __restrict__ ln_b,
              float* __restrict__ out)
{
    extern __shared__ float sm[];
    float* Ws     = sm + OFF_WS;
    float* E_s    = sm + OFF_E;
    float* sWr_s  = sm + OFF_SWR;
    float* bc_s   = sm + OFF_BC;
    float* f1s    = sm + OFF_F1S;
    float* cfs    = sm + OFF_CFS;
    float* gi_s   = sm + OFF_GI;
    float* rr_s   = sm + OFF_RR;
    float* o_s    = sm + OFF_OS;
    float* c_s    = sm + OFF_C;
    float* xm_s   = sm + OFF_XM;
    float* coef_r = sm + OFF_CR;
    float* coef_i = sm + OFF_CI;
    float* th_s   = sm + OFF_TH;
    float* d0_s   = sm + OFF_D0;
    float* ov1_s  = sm + OFF_OV1;
    float* lng_s  = sm + OFF_LNG;
    float* lnb_s  = sm + OFF_LNB;
    float* misc   = sm + OFF_MISC;

    const int tid = threadIdx.x;
    const int cta = blockIdx.x;
    const int bbase = cta * 4;
    const size_t OSTRIDE = (size_t)T_STEPS * BATCH * OUT_DIM;

    // feeders: tid 512..639 (double duty with tail GEMM warps + poller)
    const bool feeder = (tid >= 512);
    int pb = 0, pg = 0;
    float xnext = 0.0f;
    if (feeder) {
        int idx = tid - 512;
        pb = idx >> 5; pg = idx & 31;
        xnext = (pg < IN_DIM) ? xm[(size_t)(bbase + pb) * IN_DIM + pg]
                              : xa[(size_t)(bbase + pb) * AUX_DIM + (pg - IN_DIM)];
    }

    // ---- one-time smem fills ----
    for (int i = tid; i < G_DIM * R_SM; i += NTHREADS) {
        int g = i / R_SM, r = i - g * R_SM;
        Ws[i] = g_WcatT[g * NROWS + r];
    }
    for (int i = tid; i < 2048; i += NTHREADS) { E_s[i] = g_E[i]; sWr_s[i] = g_sWr[i]; }
    for (int i = tid; i < NROWS; i += NTHREADS) bc_s[i] = g_bcat[i];
    if (tid < G_DIM) d0_s[tid] = g_d0[tid];
    if (tid < OUT_DIM) { lng_s[tid] = ln_g[tid]; lnb_s[tid] = ln_b[tid]; }
    if (tid < 128) { c_s[tid] = 0.0f; cfs[tid] = 0.0f; }
    if (tid < 8) misc[tid] = 0.0f;
    if (feeder) {
        f1s[pg * 4 + pb] = xnext;
        if (pg < IN_DIM) xm_s[pb * 4 + pg] = xnext;
    }

    for (int t = 0; t < T_STEPS; ++t) {
        __syncthreads();   // sync A: carry state (cfs, c_s, f1s) ready

        // ---- feeders prefetch next-step inputs ----
        if (feeder && t + 1 < T_STEPS) {
            xnext = (pg < IN_DIM)
                ? xm[((size_t)(t + 1) * BATCH + bbase + pb) * IN_DIM + pg]
                : xa[((size_t)(t + 1) * BATCH + bbase + pb) * AUX_DIM + (pg - IN_DIM)];
        }
        // ---- poller warp 19: gather 512 partials -> S (overlaps GEMM) ----
        if (t > 0 && tid >= 608) {
            const int lane = tid - 608;
            const unsigned tg = (unsigned)t;
            const ull* base = &g_msg[t & 1][lane * 16];
            float p;
            for (;;) {
                ull v[16];
#pragma unroll
                for (int k = 0; k < 8; ++k) ld_vol_v2u64(base + 2 * k, v[2 * k], v[2 * k + 1]);
                unsigned bad = 0;
#pragma unroll
                for (int k = 0; k < 16; ++k) bad |= ((unsigned)(v[k] >> 32)) ^ tg;
                if (bad == 0) {
                    float s0 = 0.f, s1 = 0.f;
#pragma unroll
                    for (int k = 0; k < 16; k += 2) {
                        s0 += __uint_as_float((unsigned)v[k]);
                        s1 += __uint_as_float((unsigned)v[k + 1]);
                    }
                    p = s0 + s1;
                    break;
                }
            }
            p = wsum32(p);
            if (lane == 0) misc[4] = p;
        }

        // ---- GEMM: batch-packed accumulators, 2 rows/thread ----
        // a1[0]=(b0,b1)@r0  a1[1]=(b2,b3)@r0  a1[2]=(b0,b1)@r1  a1[3]=(b2,b3)@r1
        ull a1[4], a2[4];
        if (tid < NGEMM) {
#pragma unroll
            for (int k = 0; k < 4; ++k) { a1[k] = 0ull; a2[k] = 0ull; }
            const int r0 = tid * 2;
            const ulonglong2* fU = (const ulonglong2*)f1s;
            const ulonglong2* cU = (const ulonglong2*)cfs;
            if (tid < R_SM / 2) {
#pragma unroll 8
                for (int g = 0; g < 32; ++g) {
                    ulonglong2 ff = fU[g];
                    ull w = *(const ull*)(Ws + g * R_SM + r0);
                    float2 wf = unp(w);
                    ull wr0 = dup2(wf.x), wr1 = dup2(wf.y);
                    ffma2(a1[0], ff.x, wr0); ffma2(a1[1], ff.y, wr0);
                    ffma2(a1[2], ff.x, wr1); ffma2(a1[3], ff.y, wr1);
                    ulonglong2 cc = cU[g];
                    ull v = *(const ull*)(Ws + (32 + g) * R_SM + r0);
                    float2 vf = unp(v);
                    ull vr0 = dup2(vf.x), vr1 = dup2(vf.y);
                    ffma2(a2[0], cc.x, vr0); ffma2(a2[1], cc.y, vr0);
                    ffma2(a2[2], cc.x, vr1); ffma2(a2[3], cc.y, vr1);
                }
            } else {
#pragma unroll 4
                for (int g = 0; g < 32; ++g) {
                    ulonglong2 ff = fU[g];
                    ull w = __ldg((const ull*)(g_WcatT + g * NROWS + r0));
                    float2 wf = unp(w);
                    ull wr0 = dup2(wf.x), wr1 = dup2(wf.y);
                    ffma2(a1[0], ff.x, wr0); ffma2(a1[1], ff.y, wr0);
                    ffma2(a1[2], ff.x, wr1); ffma2(a1[3], ff.y, wr1);
                    ulonglong2 cc = cU[g];
                    ull v = __ldg((const ull*)(g_WcatT + (32 + g) * NROWS + r0));
                    float2 vf = unp(v);
                    ull vr0 = dup2(vf.x), vr1 = dup2(vf.y);
                    ffma2(a2[0], cc.x, vr0); ffma2(a2[1], cc.y, vr0);
                    ffma2(a2[2], cc.x, vr1); ffma2(a2[3], cc.y, vr1);
                }
            }
        }
        __syncthreads();   // sync B: misc[4] (S) visible
        const float invS = __fdividef(1.0f, misc[4] + 1e-5f);

        // ---- combine: activations + inline coef reductions + th matvec ----
        float s[4];
        if (tid < NGEMM) {
            const int r0 = tid * 2;
            float2 bb = *(const float2*)&bc_s[r0];
            float2 A0 = unp(a1[0]), A1 = unp(a1[1]), A2 = unp(a1[2]), A3 = unp(a1[3]);
            float2 B0 = unp(a2[0]), B1 = unp(a2[1]), B2 = unp(a2[2]), B3 = unp(a2[3]);
            float p0[4], p1[4];   // rows r0, r0+1 per batch
            p0[0] = fmaf(invS, B0.x, A0.x) + bb.x;
            p0[1] = fmaf(invS, B0.y, A0.y) + bb.x;
            p0[2] = fmaf(invS, B1.x, A1.x) + bb.x;
            p0[3] = fmaf(invS, B1.y, A1.y) + bb.x;
            p1[0] = fmaf(invS, B2.x, A2.x) + bb.y;
            p1[1] = fmaf(invS, B2.y, A2.y) + bb.y;
            p1[2] = fmaf(invS, B3.x, A3.x) + bb.y;
            p1[3] = fmaf(invS, B3.y, A3.y) + bb.y;
            if (r0 < 128) {
#pragma unroll
                for (int b = 0; b < 4; ++b) {
                    float v0 = sigm(p0[b]), v1 = sigm(p1[b]);
                    *(float2*)&gi_s[b * 128 + r0] = make_float2(v0, v1);
                    s[b] = v0 + v1;
                }
            } else if (r0 < 1152) {
#pragma unroll
                for (int b = 0; b < 4; ++b) {
                    float v0 = fmaxf(p0[b], 0.0f), v1 = fmaxf(p1[b], 0.0f);
                    *(float2*)&rr_s[b * 1024 + (r0 - 128)] = make_float2(v0, v1);
                    s[b] = v0 + v1;
                }
            } else {
#pragma unroll
                for (int b = 0; b < 4; ++b)
                    *(float2*)&o_s[b * 32 + (r0 - 1152)] =
                        make_float2(sigm(p0[b]), sigm(p1[b]));
            }
        }
        // th = tanh(invS * (c @ E) - d0)   (threads 0-255)
        if (tid < 256) {
            int b = tid >> 6, g = tid & 63;
            const float* cb = c_s + b * 32;
            float q0 = 0.f, q1 = 0.f;
#pragma unroll
            for (int o = 0; o < 32; o += 2) {
                q0 = fmaf(cb[o],     E_s[o * 64 + g],       q0);
                q1 = fmaf(cb[o + 1], E_s[(o + 1) * 64 + g], q1);
            }
            th_s[tid] = tanh_fast(fmaf(invS, q0 + q1, -d0_s[g]));
        }
        // half-warp reductions for coef denominators (warps 0-17 fully active)
        if (tid < 576) {
#pragma unroll
            for (int sh = 1; sh <= 8; sh <<= 1) {
                s[0] += __shfl_xor_sync(0xffffffffu, s[0], sh);
                s[1] += __shfl_xor_sync(0xffffffffu, s[1], sh);
                s[2] += __shfl_xor_sync(0xffffffffu, s[2], sh);
                s[3] += __shfl_xor_sync(0xffffffffu, s[3], sh);
            }
            if ((tid & 15) == 0) {
                if (tid < 64) {
                    int ii = tid >> 4;
#pragma unroll
                    for (int b = 0; b < 4; ++b)
                        coef_i[b * 4 + ii] = __fdividef(xm_s[b * 4 + ii], fmaxf(s[b], 1e-12f));
                } else {
                    int n = (tid - 64) >> 4;
#pragma unroll
                    for (int b = 0; b < 4; ++b)
                        coef_r[b * 32 + n] = __fdividef(c_s[b * 32 + n], fmaxf(s[b], 1e-12f));
                }
            }
        }
        __syncthreads();   // sync C

        // ---- parallel: m matvec (warps 0-3) | LayerNorm (warps 12-15) ----
        float mreg = 0.0f;
        if (tid < 128) {
            int b = tid >> 5, o = tid & 31;
            float m0, m1, m2 = 0.f, m3 = 0.f;
            m0 = coef_i[b * 4 + 0] * gi_s[b * 128 + o]
               + coef_i[b * 4 + 1] * gi_s[b * 128 + 32 + o];
            m1 = coef_i[b * 4 + 2] * gi_s[b * 128 + 64 + o]
               + coef_i[b * 4 + 3] * gi_s[b * 128 + 96 + o];
#pragma unroll
            for (int n = 0; n < 32; n += 4) {
                m0 = fmaf(coef_r[b * 32 + n],     rr_s[b * 1024 + n * 32 + o],       m0);
                m1 = fmaf(coef_r[b * 32 + n + 1], rr_s[b * 1024 + (n + 1) * 32 + o], m1);
                m2 = fmaf(coef_r[b * 32 + n + 2], rr_s[b * 1024 + (n + 2) * 32 + o], m2);
                m3 = fmaf(coef_r[b * 32 + n + 3], rr_s[b * 1024 + (n + 3) * 32 + o], m3);
            }
            mreg = (m0 + m1) + (m2 + m3);
        } else if (tid >= 384 && tid < 512) {
            int idx = tid - 384, b = idx >> 5, o = idx & 31;
            const float* thb = th_s + b * 64;
            float p0 = 0.f, p1 = 0.f, p2 = 0.f, p3 = 0.f;
#pragma unroll
            for (int g = 0; g < 64; g += 4) {
                p0 = fmaf(thb[g],     sWr_s[g * 32 + o],       p0);
                p1 = fmaf(thb[g + 1], sWr_s[(g + 1) * 32 + o], p1);
                p2 = fmaf(thb[g + 2], sWr_s[(g + 2) * 32 + o], p2);
                p3 = fmaf(thb[g + 3], sWr_s[(g + 3) * 32 + o], p3);
            }
            float pre = (p0 + p1) + (p2 + p3);
            float s1v = pre, s2v = pre * pre;
#pragma unroll
            for (int sft = 16; sft > 0; sft >>= 1) {
                s1v += __shfl_xor_sync(0xffffffffu, s1v, sft);
                s2v += __shfl_xor_sync(0xffffffffu, s2v, sft);
            }
            float mu  = s1v * (1.0f / 32.0f);
            float var = fmaxf(s2v * (1.0f / 32.0f) - mu * mu, 0.0f);
            ov1_s[idx] = (pre - mu) * rsqrtf(var + 1e-5f) * lng_s[o] + lnb_s[o];
        }
        __syncthreads();   // sync D

        // ---- tail: MR gate, outputs, carry update + publish ----
        if (tid < 128) {
            int b = tid >> 5, o = tid & 31;
            float m = mreg;
            float og  = o_s[b * 32 + o];
            float ov1 = ov1_s[b * 32 + o];
            float f = 1.0f - og;
            float ov2 = ov1 - fmaxf(ov1 - f, 0.0f);
            float MR = fmaxf(ov2 + 1.0f - f, 0.0f) + f - 1.0f;
            float opr = og + MR;
            float h = og * m;
            float cnew = (1.0f - opr) * m;
            float mrf = MR * m;

            // publish this warp's |c| row partial immediately
            float a = wsum32(fabsf(cnew));
            if (o == 0) {
                ull msg = ((ull)(unsigned)(t + 1) << 32) | (ull)__float_as_uint(a);
                *((volatile ull*)&g_msg[(t + 1) & 1][cta * 4 + b]) = msg;
            }

            size_t base = ((size_t)t * BATCH + (bbase + b)) * OUT_DIM + o;
            out[base]               = h;
            out[OSTRIDE + base]     = cnew;
            out[2 * OSTRIDE + base] = og;
            out[3 * OSTRIDE + base] = MR;
            out[4 * OSTRIDE + base] = opr;
            out[5 * OSTRIDE + base] = mrf;
            out[6 * OSTRIDE + base] = h;

            c_s[b * 32 + o] = cnew;
            cfs[o * 4 + b]  = cnew;
        } else if (feeder && t + 1 < T_STEPS) {
            f1s[pg * 4 + pb] = xnext;
            if (pg < IN_DIM) xm_s[pb * 4 + pg] = xnext;
        }
    }
}

// ---------------- launch ----------------
extern "C" void kernel_launch(void* const* d_in, const int* in_sizes, int n_in,
                              void* d_out, int out_size)
{
    const float* xm   = (const float*)d_in[0];
    const float* xa   = (const float*)d_in[1];
    const float* W_i  = (const float*)d_in[2];
    const float* b_i  = (const float*)d_in[3];
    const float* W_r  = (const float*)d_in[4];
    const float* b_r  = (const float*)d_in[5];
    const float* W_o  = (const float*)d_in[6];
    const float* b_o  = (const float*)d_in[7];
    const float* W_s  = (const float*)d_in[8];
    const float* W_rm = (const float*)d_in[9];
    const float* b0   = (const float*)d_in[10];
    const float* lng  = (const float*)d_in[11];
    const float* lnb  = (const float*)d_in[12];
    float* out = (float*)d_out;

    cudaFuncSetAttribute(mclstm_kernel, cudaFuncAttributeMaxDynamicSharedMemorySize, SMEM_BYTES);

    prep_kernel<<<320, 256>>>(W_i, b_i, W_r, b_r, W_o, b_o, W_s, W_rm, b0);
    mclstm_kernel<<<NCTA, NTHREADS, SMEM_BYTES>>>(xm, xa, lng, lnb, out);
}